// round 4
// baseline (speedup 1.0000x reference)
#include <cuda_runtime.h>
#include <cstdint>

// yoloLoss: preds (B,14,14,30) f32, truths (B,14,14,30) f32 -> scalar f32.
// Two-phase: (A) gather conf scalars for all cells (sector-sparse traffic,
// ~96B/cell instead of 240B), accumulate no-obj loss, compact obj-cell list.
// (B) full loss for the ~8% obj cells (mostly L2-resident by then).

#define BOXN    2
#define LABELN  20
#define ALL_BOX 10
#define CVALS   30
#define BATCH_INV (1.0f / 4096.0f)
#define MAX_CELLS 802816          // 4096*14*14 (fixed problem shape)

__device__ int   g_count;
__device__ int   g_list[MAX_CELLS];

// ---------------- obj-cell loss (full branch) ----------------
__device__ __forceinline__ float cell_loss_obj(const float* __restrict__ P,
                                               const float* __restrict__ T)
{
    const float conf0 = P[4];
    const float conf1 = P[9];
    const float CELLF = 1.0f / 14.0f;

    const float tcx = CELLF * T[0];
    const float tcy = CELLF * T[1];
    const float thw = 0.5f * T[2];
    const float thh = 0.5f * T[3];
    const float t_lt_x = tcx - thw, t_rb_x = tcx + thw;
    const float t_lt_y = tcy - thh, t_rb_y = tcy + thh;
    const float ta = (t_rb_x - t_lt_x) * (t_rb_y - t_lt_y);

    float iou[BOXN];
    #pragma unroll
    for (int b = 0; b < BOXN; b++) {
        const float* pb = P + 5 * b;
        const float pcx = CELLF * pb[0];
        const float pcy = CELLF * pb[1];
        const float phw = 0.5f * pb[2];
        const float phh = 0.5f * pb[3];
        const float p_lt_x = pcx - phw, p_rb_x = pcx + phw;
        const float p_lt_y = pcy - phh, p_rb_y = pcy + phh;
        const float lt_x = fmaxf(p_lt_x, t_lt_x);
        const float lt_y = fmaxf(p_lt_y, t_lt_y);
        const float rb_x = fminf(p_rb_x, t_rb_x);
        const float rb_y = fminf(p_rb_y, t_rb_y);
        const float wx = fmaxf(rb_x - lt_x, 0.0f);
        const float wy = fmaxf(rb_y - lt_y, 0.0f);
        const float inter = wx * wy;
        const float pa = (p_rb_x - p_lt_x) * (p_rb_y - p_lt_y);
        iou[b] = inter / (pa + ta - inter);
    }

    // responsible box: jnp argmax-first-index tie semantics
    int resp;
    if (iou[0] == iou[1]) resp = (conf1 > conf0) ? 1 : 0;
    else                  resp = (iou[1] > iou[0]) ? 1 : 0;
    const float max_iou = fmaxf(iou[0], iou[1]);

    const float* pr = P + 5 * resp;
    const float other_conf = (resp == 0) ? conf1 : conf0;

    const float dx = pr[0] - T[0];
    const float dy = pr[1] - T[1];
    const float dw = sqrtf(pr[2]) - sqrtf(T[2]);
    const float dh = sqrtf(pr[3]) - sqrtf(T[3]);
    float c = 5.0f * (dx * dx + dy * dy + dw * dw + dh * dh);

    const float dc = pr[4] - max_iou;
    c += dc * dc;
    c += 0.5f * other_conf * other_conf;

    #pragma unroll
    for (int k = 0; k < LABELN; k++) {
        const float d = P[ALL_BOX + k] - T[ALL_BOX + k];
        c += d * d;
    }
    return c;
}

// ---------------- block reduce + atomic ----------------
__device__ __forceinline__ void block_reduce_add(float acc, float* out,
                                                 float scale, int tid, int nthreads)
{
    #pragma unroll
    for (int off = 16; off > 0; off >>= 1)
        acc += __shfl_down_sync(0xFFFFFFFFu, acc, off);

    __shared__ float warp_sums[8];
    const int warp = tid >> 5;
    const int lane = tid & 31;
    if (lane == 0) warp_sums[warp] = acc;
    __syncthreads();
    if (tid == 0) {
        float s = 0.0f;
        const int nw = nthreads >> 5;
        for (int w = 0; w < nw; w++) s += warp_sums[w];
        atomicAdd(out, s * scale);
    }
}

// ---------------- Kernel A: conf gather + noobj sum + obj list ----------------
#define A_THREADS 256
#define A_PER_THREAD 4

__global__ void __launch_bounds__(A_THREADS)
yolo_gather_kernel(const float* __restrict__ preds,
                   const float* __restrict__ truths,
                   float* __restrict__ out,
                   int n_cells, float batch_inv)
{
    const int tid    = threadIdx.x;
    const int gtid   = blockIdx.x * A_THREADS + tid;
    const int stride = gridDim.x * A_THREADS;

    float t4[A_PER_THREAD], p4[A_PER_THREAD], p9[A_PER_THREAD];
    int   c[A_PER_THREAD];
    bool  v[A_PER_THREAD];

    float acc = 0.0f;

    #pragma unroll
    for (int k = 0; k < A_PER_THREAD; k++) {
        c[k] = gtid + k * stride;
        v[k] = c[k] < n_cells;
        const int b = c[k] * CVALS;
        t4[k] = v[k] ? __ldg(truths + b + 4) : 0.0f;
        p4[k] = v[k] ? __ldg(preds  + b + 4) : 0.0f;
        p9[k] = v[k] ? __ldg(preds  + b + 9) : 0.0f;
    }

    #pragma unroll
    for (int k = 0; k < A_PER_THREAD; k++) {
        const bool obj = v[k] && (t4[k] > 0.0f);
        if (!obj) acc += 0.5f * (p4[k] * p4[k] + p9[k] * p9[k]);

        // warp-aggregated append of obj cell indices
        const unsigned m = __ballot_sync(0xFFFFFFFFu, obj);
        if (obj) {
            const int lane   = tid & 31;
            const int leader = __ffs(m) - 1;
            int base;
            if (lane == leader) base = atomicAdd(&g_count, __popc(m));
            base = __shfl_sync(m, base, leader);
            const int rank = __popc(m & ((1u << lane) - 1));
            const int slot = base + rank;
            if (slot < MAX_CELLS) g_list[slot] = c[k];
        }
    }

    block_reduce_add(acc, out, batch_inv, tid, A_THREADS);
}

// ---------------- Kernel B: full loss for obj cells ----------------
#define B_THREADS 128

__global__ void __launch_bounds__(B_THREADS)
yolo_obj_kernel(const float* __restrict__ preds,
                const float* __restrict__ truths,
                float* __restrict__ out,
                float batch_inv)
{
    __shared__ float sP[B_THREADS * CVALS];
    __shared__ float sT[B_THREADS * CVALS];
    __shared__ int   sIdx[B_THREADS];

    const int tid   = threadIdx.x;
    const int count = g_count;                // written by kernel A (stream order)
    const int base  = blockIdx.x * B_THREADS;
    if (base >= count) return;
    const int n = min(B_THREADS, count - base);

    for (int i = tid; i < n; i += B_THREADS) sIdx[i] = g_list[base + i];
    __syncthreads();

    // cooperative staging: 60 floats per cell, coalesced within a cell
    for (int e = tid; e < n * (2 * CVALS); e += B_THREADS) {
        const int cl = e / (2 * CVALS);
        const int f  = e - cl * (2 * CVALS);
        const int g  = sIdx[cl] * CVALS;
        if (f < CVALS) sP[cl * CVALS + f]         = __ldg(preds  + g + f);
        else           sT[cl * CVALS + f - CVALS] = __ldg(truths + g + f - CVALS);
    }
    __syncthreads();

    float acc = 0.0f;
    if (tid < n)
        acc = cell_loss_obj(sP + tid * CVALS, sT + tid * CVALS);

    block_reduce_add(acc, out, batch_inv, tid, B_THREADS);
}

// ---------------- launch ----------------
extern "C" void kernel_launch(void* const* d_in, const int* in_sizes, int n_in,
                              void* d_out, int out_size)
{
    const float* preds  = (const float*)d_in[0];
    const float* truths = (const float*)d_in[1];
    float* out = (float*)d_out;

    const int n_cells = in_sizes[0] / CVALS;   // 802816

    void* count_addr = nullptr;
    cudaGetSymbolAddress(&count_addr, g_count);

    cudaMemsetAsync(d_out, 0, sizeof(float), 0);
    cudaMemsetAsync(count_addr, 0, sizeof(int), 0);

    const int a_threads_total = (n_cells + A_PER_THREAD - 1) / A_PER_THREAD;
    const int a_blocks = (a_threads_total + A_THREADS - 1) / A_THREADS;   // ~784
    yolo_gather_kernel<<<a_blocks, A_THREADS, 0, 0>>>(preds, truths, out,
                                                      n_cells, BATCH_INV);

    const int b_blocks = (n_cells + B_THREADS - 1) / B_THREADS;  // upper bound; early exit
    yolo_obj_kernel<<<b_blocks, B_THREADS, 0, 0>>>(preds, truths, out, BATCH_INV);
}

// round 5
// speedup vs baseline: 1.8212x; 1.8212x over previous
#include <cuda_runtime.h>
#include <cstdint>

// yoloLoss: preds (B,14,14,30) f32, truths (B,14,14,30) f32 -> scalar f32.
// Single-pass sparse-read kernel: only conf scalars (T[4],P[4],P[9]) are read
// for the ~92% no-object cells (~80B of DRAM sectors/cell instead of 240B);
// full 60-float cell read only on the ~8% object branch. ~75MB total traffic.

#define BOXN    2
#define LABELN  20
#define ALL_BOX 10
#define CVALS   30
#define BATCH_INV (1.0f / 4096.0f)

#define NTHREADS 256
#define PT 4                 // cells per thread

// full loss for an object cell; conf0/conf1 already loaded.
// base pointers are to the cell's 30 floats; cell*120B is 8B-aligned -> float2 ok.
__device__ __forceinline__ float cell_loss_obj(const float* __restrict__ Pp,
                                               const float* __restrict__ Tp,
                                               float conf0, float conf1)
{
    const float2* P2 = reinterpret_cast<const float2*>(Pp);
    const float2* T2 = reinterpret_cast<const float2*>(Tp);

    // P[0..9] as 5 float2, T[0..3] as 2 float2
    const float2 p01 = __ldg(P2 + 0);
    const float2 p23 = __ldg(P2 + 1);
    const float2 p45 = __ldg(P2 + 2);   // .y = P[5]
    const float2 p67 = __ldg(P2 + 3);
    const float2 p89 = __ldg(P2 + 4);   // .x = P[8]
    const float2 t01 = __ldg(T2 + 0);
    const float2 t23 = __ldg(T2 + 1);

    const float CELLF = 1.0f / 14.0f;

    const float tcx = CELLF * t01.x;
    const float tcy = CELLF * t01.y;
    const float thw = 0.5f * t23.x;
    const float thh = 0.5f * t23.y;
    const float t_lt_x = tcx - thw, t_rb_x = tcx + thw;
    const float t_lt_y = tcy - thh, t_rb_y = tcy + thh;
    const float ta = (t_rb_x - t_lt_x) * (t_rb_y - t_lt_y);

    const float bx[BOXN] = { p01.x, p45.y };
    const float by[BOXN] = { p01.y, p67.x };
    const float bw[BOXN] = { p23.x, p67.y };
    const float bh[BOXN] = { p23.y, p89.x };

    float iou[BOXN];
    #pragma unroll
    for (int b = 0; b < BOXN; b++) {
        const float pcx = CELLF * bx[b];
        const float pcy = CELLF * by[b];
        const float phw = 0.5f * bw[b];
        const float phh = 0.5f * bh[b];
        const float p_lt_x = pcx - phw, p_rb_x = pcx + phw;
        const float p_lt_y = pcy - phh, p_rb_y = pcy + phh;
        const float lt_x = fmaxf(p_lt_x, t_lt_x);
        const float lt_y = fmaxf(p_lt_y, t_lt_y);
        const float rb_x = fminf(p_rb_x, t_rb_x);
        const float rb_y = fminf(p_rb_y, t_rb_y);
        const float wx = fmaxf(rb_x - lt_x, 0.0f);
        const float wy = fmaxf(rb_y - lt_y, 0.0f);
        const float inter = wx * wy;
        const float pa = (p_rb_x - p_lt_x) * (p_rb_y - p_lt_y);
        iou[b] = inter / (pa + ta - inter);
    }

    // responsible box: jnp argmax-first-index tie semantics
    int resp;
    if (iou[0] == iou[1]) resp = (conf1 > conf0) ? 1 : 0;
    else                  resp = (iou[1] > iou[0]) ? 1 : 0;
    const float max_iou = fmaxf(iou[0], iou[1]);

    const float rx = (resp == 0) ? bx[0] : bx[1];
    const float ry = (resp == 0) ? by[0] : by[1];
    const float rw = (resp == 0) ? bw[0] : bw[1];
    const float rh = (resp == 0) ? bh[0] : bh[1];
    const float rconf      = (resp == 0) ? conf0 : conf1;
    const float other_conf = (resp == 0) ? conf1 : conf0;

    const float dx = rx - t01.x;
    const float dy = ry - t01.y;
    const float dw = sqrtf(rw) - sqrtf(t23.x);
    const float dh = sqrtf(rh) - sqrtf(t23.y);
    float c = 5.0f * (dx * dx + dy * dy + dw * dw + dh * dh);

    const float dc = rconf - max_iou;
    c += dc * dc;
    c += 0.5f * other_conf * other_conf;

    // labels: P[10..29], T[10..29] as 10 float2 each
    #pragma unroll
    for (int k = 0; k < LABELN / 2; k++) {
        const float2 pl = __ldg(P2 + 5 + k);
        const float2 tl = __ldg(T2 + 5 + k);
        const float d0 = pl.x - tl.x;
        const float d1 = pl.y - tl.y;
        c += d0 * d0 + d1 * d1;
    }
    return c;
}

__global__ void __launch_bounds__(NTHREADS)
yolo_loss_kernel(const float* __restrict__ preds,
                 const float* __restrict__ truths,
                 float* __restrict__ out,
                 int n_cells, float batch_inv)
{
    const int tid    = threadIdx.x;
    const int gtid   = blockIdx.x * NTHREADS + tid;
    const int stride = gridDim.x * NTHREADS;

    float t4[PT], p4[PT], p9[PT];
    int   c[PT];

    // batched conf loads: 12 independent LDGs in flight per thread
    #pragma unroll
    for (int k = 0; k < PT; k++) {
        c[k] = gtid + k * stride;
        const bool v = c[k] < n_cells;
        const long long b = (long long)c[k] * CVALS;
        t4[k] = v ? __ldg(truths + b + 4) : 0.0f;
        p4[k] = v ? __ldg(preds  + b + 4) : 0.0f;
        p9[k] = v ? __ldg(preds  + b + 9) : 0.0f;
    }

    float acc = 0.0f;
    #pragma unroll
    for (int k = 0; k < PT; k++) {
        if (t4[k] > 0.0f) {
            const long long b = (long long)c[k] * CVALS;
            acc += cell_loss_obj(preds + b, truths + b, p4[k], p9[k]);
        } else {
            acc += 0.5f * (p4[k] * p4[k] + p9[k] * p9[k]);
        }
    }

    // block reduction -> one atomic per CTA
    #pragma unroll
    for (int off = 16; off > 0; off >>= 1)
        acc += __shfl_down_sync(0xFFFFFFFFu, acc, off);

    __shared__ float warp_sums[NTHREADS / 32];
    const int warp = tid >> 5;
    const int lane = tid & 31;
    if (lane == 0) warp_sums[warp] = acc;
    __syncthreads();

    if (tid == 0) {
        float s = 0.0f;
        #pragma unroll
        for (int w = 0; w < NTHREADS / 32; w++) s += warp_sums[w];
        atomicAdd(out, s * batch_inv);
    }
}

extern "C" void kernel_launch(void* const* d_in, const int* in_sizes, int n_in,
                              void* d_out, int out_size)
{
    const float* preds  = (const float*)d_in[0];
    const float* truths = (const float*)d_in[1];
    float* out = (float*)d_out;

    const int n_cells = in_sizes[0] / CVALS;                      // 802816
    const int total_threads = (n_cells + PT - 1) / PT;
    const int blocks = (total_threads + NTHREADS - 1) / NTHREADS; // ~784

    cudaMemsetAsync(d_out, 0, sizeof(float), 0);
    yolo_loss_kernel<<<blocks, NTHREADS, 0, 0>>>(preds, truths, out,
                                                 n_cells, BATCH_INV);
}

// round 6
// speedup vs baseline: 2.0394x; 1.1198x over previous
#include <cuda_runtime.h>
#include <cstdint>

// yoloLoss: preds (B,14,14,30) f32, truths (B,14,14,30) f32 -> scalar f32.
// Persistent-CTA 2-stage cp.async pipeline, tuned for occupancy:
// TILE=64 cells -> 30KB smem/CTA -> 7 CTAs/SM, grid=896 -> exactly 14
// tiles per CTA (802816/64 = 12544 = 896*14), zero tail imbalance.

#define BOXN    2
#define LABELN  20
#define ALL_BOX 10
#define CVALS   30
#define BATCH_INV (1.0f / 4096.0f)

#define TILE    64                        // cells per tile
#define TFLOATS (TILE * CVALS)            // 1920 floats per tensor per tile
#define CHUNKS  (TFLOATS / 4)             // 480 16B chunks per tensor
#define STAGE_FLOATS (2 * TFLOATS)        // 3840
#define SMEM_BYTES (2 * STAGE_FLOATS * 4) // 30720
#define NBLOCKS 896                       // 12544 tiles / 14 = 896 (single wave)

__device__ __forceinline__ void cp16(uint32_t dst, const float* src) {
    asm volatile("cp.async.cg.shared.global [%0], [%1], 16;" :: "r"(dst), "l"(src));
}
__device__ __forceinline__ void cp_commit() {
    asm volatile("cp.async.commit_group;");
}
__device__ __forceinline__ void cp_wait1() {
    asm volatile("cp.async.wait_group 1;");
}

__device__ __forceinline__ float cell_loss(const float* __restrict__ P,
                                           const float* __restrict__ T)
{
    const float conf0 = P[4];
    const float conf1 = P[9];
    const float tconf = T[4];

    if (tconf > 0.0f) {
        const float CELLF = 1.0f / 14.0f;
        const float tcx = CELLF * T[0];
        const float tcy = CELLF * T[1];
        const float thw = 0.5f * T[2];
        const float thh = 0.5f * T[3];
        const float t_lt_x = tcx - thw, t_rb_x = tcx + thw;
        const float t_lt_y = tcy - thh, t_rb_y = tcy + thh;
        const float ta = (t_rb_x - t_lt_x) * (t_rb_y - t_lt_y);

        float iou[BOXN];
        #pragma unroll
        for (int b = 0; b < BOXN; b++) {
            const float* pb = P + 5 * b;
            const float pcx = CELLF * pb[0];
            const float pcy = CELLF * pb[1];
            const float phw = 0.5f * pb[2];
            const float phh = 0.5f * pb[3];
            const float p_lt_x = pcx - phw, p_rb_x = pcx + phw;
            const float p_lt_y = pcy - phh, p_rb_y = pcy + phh;
            const float lt_x = fmaxf(p_lt_x, t_lt_x);
            const float lt_y = fmaxf(p_lt_y, t_lt_y);
            const float rb_x = fminf(p_rb_x, t_rb_x);
            const float rb_y = fminf(p_rb_y, t_rb_y);
            const float wx = fmaxf(rb_x - lt_x, 0.0f);
            const float wy = fmaxf(rb_y - lt_y, 0.0f);
            const float inter = wx * wy;
            const float pa = (p_rb_x - p_lt_x) * (p_rb_y - p_lt_y);
            iou[b] = inter / (pa + ta - inter);
        }

        // responsible box: jnp argmax-first-index tie semantics
        int resp;
        if (iou[0] == iou[1]) resp = (conf1 > conf0) ? 1 : 0;
        else                  resp = (iou[1] > iou[0]) ? 1 : 0;
        const float max_iou = fmaxf(iou[0], iou[1]);

        const float* pr = P + 5 * resp;
        const float other_conf = (resp == 0) ? conf1 : conf0;

        const float dx = pr[0] - T[0];
        const float dy = pr[1] - T[1];
        const float dw = sqrtf(pr[2]) - sqrtf(T[2]);
        const float dh = sqrtf(pr[3]) - sqrtf(T[3]);
        float c = 5.0f * (dx * dx + dy * dy + dw * dw + dh * dh);

        const float dc = pr[4] - max_iou;
        c += dc * dc;
        c += 0.5f * other_conf * other_conf;

        #pragma unroll
        for (int k = 0; k < LABELN; k++) {
            const float d = P[ALL_BOX + k] - T[ALL_BOX + k];
            c += d * d;
        }
        return c;
    } else {
        return 0.5f * (conf0 * conf0 + conf1 * conf1);
    }
}

__device__ __forceinline__ void prefetch_tile(int tile, int stage,
                                              const float* __restrict__ preds,
                                              const float* __restrict__ truths,
                                              uint32_t sbase, int tid)
{
    const long long base = (long long)tile * TFLOATS;
    const float* gp = preds + base;
    const float* gt = truths + base;
    const uint32_t s = sbase + (uint32_t)stage * (STAGE_FLOATS * 4);
    // 960 16B chunks / 64 threads = 15 per thread
    #pragma unroll
    for (int k = 0; k < 15; k++) {
        const int idx = k * TILE + tid;          // 0..959
        if (idx < CHUNKS) {
            cp16(s + idx * 16, gp + idx * 4);
        } else {
            const int j = idx - CHUNKS;
            cp16(s + TFLOATS * 4 + j * 16, gt + j * 4);
        }
    }
}

extern __shared__ float smem[];

__global__ void __launch_bounds__(TILE)
yolo_loss_kernel(const float* __restrict__ preds,
                 const float* __restrict__ truths,
                 float* __restrict__ out,
                 int n_tiles, int n_cells, float batch_inv)
{
    const int tid = threadIdx.x;
    const uint32_t sbase = (uint32_t)__cvta_generic_to_shared(smem);

    float acc = 0.0f;

    const int t0 = blockIdx.x;
    if (t0 < n_tiles)
        prefetch_tile(t0, 0, preds, truths, sbase, tid);
    cp_commit();

    int stage = 0;
    for (int t = t0; t < n_tiles; t += gridDim.x) {
        const int tn = t + gridDim.x;
        if (tn < n_tiles)
            prefetch_tile(tn, stage ^ 1, preds, truths, sbase, tid);
        cp_commit();
        cp_wait1();            // FIFO retirement -> tile t resident
        __syncthreads();

        const float* P = smem + stage * STAGE_FLOATS + tid * CVALS;
        const float* T = P + TFLOATS;
        acc += cell_loss(P, T);

        __syncthreads();       // protect stage before it is re-filled
        stage ^= 1;
    }

    // generic remainder (n_cells not a multiple of TILE): block 0, direct loads
    if (blockIdx.x == 0) {
        const int cell = n_tiles * TILE + tid;
        if (cell < n_cells)
            acc += cell_loss(preds + (long long)cell * CVALS,
                             truths + (long long)cell * CVALS);
    }

    // block reduction (2 warps) -> one atomic per CTA
    #pragma unroll
    for (int off = 16; off > 0; off >>= 1)
        acc += __shfl_down_sync(0xFFFFFFFFu, acc, off);

    __shared__ float warp_sums[TILE / 32];
    const int warp = tid >> 5;
    const int lane = tid & 31;
    if (lane == 0) warp_sums[warp] = acc;
    __syncthreads();

    if (tid == 0) {
        float s = 0.0f;
        #pragma unroll
        for (int w = 0; w < TILE / 32; w++) s += warp_sums[w];
        atomicAdd(out, s * batch_inv);
    }
}

extern "C" void kernel_launch(void* const* d_in, const int* in_sizes, int n_in,
                              void* d_out, int out_size)
{
    const float* preds  = (const float*)d_in[0];
    const float* truths = (const float*)d_in[1];
    float* out = (float*)d_out;

    const int n_cells = in_sizes[0] / CVALS;     // 802816
    const int n_tiles = n_cells / TILE;          // 12544

    cudaFuncSetAttribute(yolo_loss_kernel,
                         cudaFuncAttributeMaxDynamicSharedMemorySize, SMEM_BYTES);

    cudaMemsetAsync(d_out, 0, sizeof(float), 0);
    yolo_loss_kernel<<<NBLOCKS, TILE, SMEM_BYTES, 0>>>(preds, truths, out,
                                                       n_tiles, n_cells, BATCH_INV);
}